// round 1
// baseline (speedup 1.0000x reference)
#include <cuda_runtime.h>
#include <math.h>

#define BB 8
#define C4v 64
#define OQ 16
#define NNv 512
#define LL 12
#define CCv (OQ * C4v)   // 1024

// Scratch (device globals: allocation-free per harness rules)
__device__ float g_G[BB * NNv * CCv];   // [b][n][c'][c]  16.8 MB
__device__ float g_Fl[BB * NNv * OQ];   // [b][n][c']
__device__ float g_T[BB * NNv * NNv];   // [b][k][n]      8.4 MB
__device__ float g_H[BB * NNv * CCv];   // [b][k][cc]     16.8 MB
__device__ float g_xx[BB * OQ];
__device__ float g_yy[BB * OQ];
__device__ float g_invl2[BB];

__global__ void k_zero() {
    int t = threadIdx.x;
    if (t < BB * OQ) { g_xx[t] = 0.f; g_yy[t] = 0.f; }
}

// k1: Fc (local), Fl, G, norm partials. Block per (n, b), 128 threads.
__global__ void k1(const float* __restrict__ x, const float* __restrict__ Wc,
                   const float* __restrict__ bc) {
    int n = blockIdx.x, b = blockIdx.y;
    __shared__ float xs[C4v * LL];   // [c][l]
    __shared__ float Ws[OQ * C4v];   // [o][c]
    __shared__ float Fc[OQ * LL];    // [o][l]
    int t = threadIdx.x;

    for (int i = t; i < C4v * LL; i += 128) {
        int c = i / LL, l = i % LL;
        xs[i] = x[((b * C4v + c) * NNv + n) * LL + l];
    }
    for (int i = t; i < OQ * C4v; i += 128) Ws[i] = Wc[i];
    __syncthreads();

    for (int i = t; i < OQ * LL; i += 128) {
        int o = i / LL, l = i % LL;
        float s = bc[o];
        #pragma unroll 16
        for (int c = 0; c < C4v; c++) s += Ws[o * C4v + c] * xs[c * LL + l];
        Fc[i] = s;
    }
    __syncthreads();

    // G[b][n][o][c] = sum_l Fc[o][l] * x[c][l]
    for (int i = t; i < CCv; i += 128) {
        int o = i >> 6, c = i & 63;
        float s = 0.f;
        #pragma unroll
        for (int l = 0; l < LL; l++) s += Fc[o * LL + l] * xs[c * LL + l];
        g_G[(b * NNv + n) * CCv + i] = s;
    }
    if (t < OQ) {
        float fl = Fc[t * LL + (LL - 1)];
        g_Fl[(b * NNv + n) * OQ + t] = fl;
        float ys = 0.f;
        #pragma unroll
        for (int l = 0; l < LL; l++) { float v = Fc[t * LL + l]; ys += v * v; }
        atomicAdd(&g_xx[b * OQ + t], fl * fl);
        atomicAdd(&g_yy[b * OQ + t], ys);
    }
}

// k1b: inv_l2[b] = 1 / sum_c sqrt(xx)*sqrt(yy)
__global__ void k1b() {
    int b = blockIdx.x;
    int t = threadIdx.x;  // 32
    float v = 0.f;
    if (t < OQ) v = sqrtf(g_xx[b * OQ + t]) * sqrtf(g_yy[b * OQ + t]);
    #pragma unroll
    for (int s = 16; s > 0; s >>= 1) v += __shfl_down_sync(0xffffffffu, v, s);
    if (t == 0) g_invl2[b] = 1.0f / v;
}

// k2: T[b][p][q] = relu(tanh(inv * max_c sum_o Fl[b][q][o] * G[b][p][o][c]))
// Block per (p, b), 256 threads, 2 q per thread.
__global__ void k2() {
    int p = blockIdx.x, b = blockIdx.y;
    __shared__ float Fls[NNv * OQ];  // 32 KB
    __shared__ float Gp[CCv];        // 4 KB
    int t = threadIdx.x;  // 256

    {
        const float4* src = (const float4*)(g_Fl + (size_t)b * NNv * OQ);
        float4* dst = (float4*)Fls;
        for (int i = t; i < NNv * OQ / 4; i += 256) dst[i] = src[i];
        const float4* gsrc = (const float4*)(g_G + ((size_t)b * NNv + p) * CCv);
        if (t < CCv / 4) ((float4*)Gp)[t] = gsrc[t];
    }
    __syncthreads();

    float inv = g_invl2[b];
    float fl0[OQ], fl1[OQ];
    #pragma unroll
    for (int o = 0; o < OQ; o++) {
        fl0[o] = Fls[t * OQ + o];
        fl1[o] = Fls[(t + 256) * OQ + o];
    }
    float m0 = -1e30f, m1 = -1e30f;
    for (int c = 0; c < C4v; c++) {
        float a0 = 0.f, a1 = 0.f;
        #pragma unroll
        for (int o = 0; o < OQ; o++) {
            float g = Gp[o * C4v + c];     // uniform -> broadcast LDS
            a0 += fl0[o] * g;
            a1 += fl1[o] * g;
        }
        m0 = fmaxf(m0, a0);
        m1 = fmaxf(m1, a1);
    }
    float* Trow = g_T + ((size_t)b * NNv + p) * NNv;
    Trow[t]       = fmaxf(tanhf(m0 * inv), 0.f);
    Trow[t + 256] = fmaxf(tanhf(m1 * inv), 0.f);
}

// k3: per-b SGEMM  H[k][cc] = sum_n G[n][cc] * T[k][n]
// 64x64 tile, Kt=16, 256 threads, 4x4 microtile.
__global__ void k3() {
    int b = blockIdx.z;
    int cc0 = blockIdx.y * 64;
    int k0 = blockIdx.x * 64;
    const float* A  = g_G + (size_t)b * NNv * CCv;  // [n][cc]
    const float* Bm = g_T + (size_t)b * NNv * NNv;  // [k][n]
    float* Cm = g_H + (size_t)b * NNv * CCv;        // [k][cc]

    __shared__ float As[16][64];
    __shared__ float Bs[16][68];
    int t = threadIdx.x;
    int tx = t & 15, ty = t >> 4;
    float acc[4][4] = {};

    for (int n0 = 0; n0 < NNv; n0 += 16) {
        {   // stage A tile [16 n][64 cc]
            int row = t >> 4;
            int col = (t & 15) * 4;
            float4 v = *(const float4*)(A + (size_t)(n0 + row) * CCv + cc0 + col);
            *(float4*)(&As[row][col]) = v;
        }
        {   // stage B tile transposed: Bs[n][k]
            int k  = t >> 2;
            int nn = (t & 3) * 4;
            float4 v = *(const float4*)(Bm + (size_t)(k0 + k) * NNv + n0 + nn);
            Bs[nn + 0][k] = v.x; Bs[nn + 1][k] = v.y;
            Bs[nn + 2][k] = v.z; Bs[nn + 3][k] = v.w;
        }
        __syncthreads();
        #pragma unroll
        for (int kk = 0; kk < 16; kk++) {
            float a[4], bb[4];
            #pragma unroll
            for (int i = 0; i < 4; i++) a[i] = As[kk][tx * 4 + i];
            #pragma unroll
            for (int j = 0; j < 4; j++) bb[j] = Bs[kk][ty * 4 + j];
            #pragma unroll
            for (int j = 0; j < 4; j++)
                #pragma unroll
                for (int i = 0; i < 4; i++) acc[i][j] += a[i] * bb[j];
        }
        __syncthreads();
    }
    #pragma unroll
    for (int j = 0; j < 4; j++) {
        float4 v = make_float4(acc[0][j], acc[1][j], acc[2][j], acc[3][j]);
        *(float4*)(Cm + (size_t)(k0 + ty * 4 + j) * CCv + cc0 + tx * 4) = v;
    }
}

// k4: xg[c][k] = inv * sum_o Fl[b][k][o] * H[b][k][o*64+c];
//     out[b][o][k] = b_gcn[o] + sum_c W_gcn[o][c] * xg[c][k]
__global__ void k4(const float* __restrict__ Wg, const float* __restrict__ bg,
                   float* __restrict__ out) {
    int k = blockIdx.x, b = blockIdx.y;
    __shared__ float Hs[CCv];
    __shared__ float xg[C4v];
    __shared__ float Wgs[C4v * C4v];
    __shared__ float Flk[OQ];
    int t = threadIdx.x;  // 128

    for (int i = t; i < CCv / 4; i += 128)
        ((float4*)Hs)[i] = ((const float4*)(g_H + ((size_t)b * NNv + k) * CCv))[i];
    for (int i = t; i < C4v * C4v / 4; i += 128)
        ((float4*)Wgs)[i] = ((const float4*)Wg)[i];
    if (t < OQ) Flk[t] = g_Fl[((size_t)b * NNv + k) * OQ + t];
    __syncthreads();

    float inv = g_invl2[b];
    if (t < C4v) {
        float s = 0.f;
        #pragma unroll
        for (int o = 0; o < OQ; o++) s += Flk[o] * Hs[o * C4v + t];
        xg[t] = s * inv;
    }
    __syncthreads();
    if (t < C4v) {
        float s = bg[t];
        #pragma unroll 16
        for (int c = 0; c < C4v; c++) s += Wgs[t * C4v + c] * xg[c];
        out[((size_t)b * C4v + t) * NNv + k] = s;
    }
}

extern "C" void kernel_launch(void* const* d_in, const int* in_sizes, int n_in,
                              void* d_out, int out_size) {
    const float* x  = (const float*)d_in[0];
    const float* Wc = (const float*)d_in[1];
    const float* bc = (const float*)d_in[2];
    const float* Wg = (const float*)d_in[3];
    const float* bg = (const float*)d_in[4];
    float* out = (float*)d_out;

    k_zero<<<1, 256>>>();
    k1<<<dim3(NNv, BB), 128>>>(x, Wc, bc);
    k1b<<<BB, 32>>>();
    k2<<<dim3(NNv, BB), 256>>>();
    k3<<<dim3(NNv / 64, CCv / 64, BB), 256>>>();
    k4<<<dim3(NNv, BB), 128>>>(Wg, bg, out);
}

// round 3
// speedup vs baseline: 1.0746x; 1.0746x over previous
#include <cuda_runtime.h>
#include <math.h>

#define BB 8
#define C4v 64
#define OQ 16
#define NNv 512
#define LL 12
#define CCv (OQ * C4v)   // 1024

typedef unsigned long long ull;

__device__ __forceinline__ ull pk(float lo, float hi) {
    ull r; asm("mov.b64 %0,{%1,%2};" : "=l"(r) : "f"(lo), "f"(hi)); return r;
}
__device__ __forceinline__ void upk(ull v, float& lo, float& hi) {
    asm("mov.b64 {%0,%1},%2;" : "=f"(lo), "=f"(hi) : "l"(v));
}
__device__ __forceinline__ ull fma2(ull a, ull b, ull c) {
    ull d; asm("fma.rn.f32x2 %0,%1,%2,%3;" : "=l"(d) : "l"(a), "l"(b), "l"(c)); return d;
}
__device__ __forceinline__ ull mul2(ull a, ull b) {
    ull d; asm("mul.rn.f32x2 %0,%1,%2;" : "=l"(d) : "l"(a), "l"(b)); return d;
}

// Scratch (device globals: allocation-free per harness rules)
__device__ float g_G[BB * NNv * CCv];   // [b][n][c'][c]  16.8 MB
__device__ float g_Fl[BB * NNv * OQ];   // [b][n][c']
__device__ float g_T[BB * NNv * NNv];   // [b][k][n]      8.4 MB
__device__ float g_H[BB * NNv * CCv];   // [b][k][cc]     16.8 MB
__device__ float g_xx[BB * OQ];
__device__ float g_yy[BB * OQ];
__device__ float g_invl2[BB];

__global__ void k_zero() {
    int t = threadIdx.x;
    if (t < BB * OQ) { g_xx[t] = 0.f; g_yy[t] = 0.f; }
}

// k1: Fc (local), Fl, G, norm partials. Block per (n, b), 128 threads.
__global__ void k1(const float* __restrict__ x, const float* __restrict__ Wc,
                   const float* __restrict__ bc) {
    int n = blockIdx.x, b = blockIdx.y;
    __shared__ float xs[C4v * LL];   // [c][l]
    __shared__ float Ws[OQ * C4v];   // [o][c]
    __shared__ float Fc[OQ * LL];    // [o][l]
    int t = threadIdx.x;

    for (int i = t; i < C4v * LL; i += 128) {
        int c = i / LL, l = i % LL;
        xs[i] = x[((b * C4v + c) * NNv + n) * LL + l];
    }
    for (int i = t; i < OQ * C4v; i += 128) Ws[i] = Wc[i];
    __syncthreads();

    for (int i = t; i < OQ * LL; i += 128) {
        int o = i / LL, l = i % LL;
        float s = bc[o];
        #pragma unroll 16
        for (int c = 0; c < C4v; c++) s += Ws[o * C4v + c] * xs[c * LL + l];
        Fc[i] = s;
    }
    __syncthreads();

    // G[b][n][o][c] = sum_l Fc[o][l] * x[c][l]
    for (int i = t; i < CCv; i += 128) {
        int o = i >> 6, c = i & 63;
        float s = 0.f;
        #pragma unroll
        for (int l = 0; l < LL; l++) s += Fc[o * LL + l] * xs[c * LL + l];
        g_G[(b * NNv + n) * CCv + i] = s;
    }
    if (t < OQ) {
        float fl = Fc[t * LL + (LL - 1)];
        g_Fl[(b * NNv + n) * OQ + t] = fl;
        float ys = 0.f;
        #pragma unroll
        for (int l = 0; l < LL; l++) { float v = Fc[t * LL + l]; ys += v * v; }
        atomicAdd(&g_xx[b * OQ + t], fl * fl);
        atomicAdd(&g_yy[b * OQ + t], ys);
    }
}

// k1b: inv_l2[b] = 1 / sum_c sqrt(xx)*sqrt(yy)
__global__ void k1b() {
    int b = blockIdx.x;
    int t = threadIdx.x;  // 32
    float v = 0.f;
    if (t < OQ) v = sqrtf(g_xx[b * OQ + t]) * sqrtf(g_yy[b * OQ + t]);
    #pragma unroll
    for (int s = 16; s > 0; s >>= 1) v += __shfl_down_sync(0xffffffffu, v, s);
    if (t == 0) g_invl2[b] = 1.0f / v;
}

// k2: T[b][p][q] = relu(tanh(inv * max_c sum_o Fl[b][q][o] * G[b][p][o][c]))
// Block per (p, b), 128 threads, 4 q per thread, f32x2 packed over q-pairs.
__global__ void __launch_bounds__(128) k2() {
    int p = blockIdx.x, b = blockIdx.y;
    __shared__ float Fls[NNv * OQ];  // 32 KB  [q][o]
    __shared__ ull Gd[OQ * C4v];     // 8 KB   (g,g) duplicated pairs
    int t = threadIdx.x;  // 128

    {
        const float4* src = (const float4*)(g_Fl + (size_t)b * NNv * OQ);
        float4* dst = (float4*)Fls;
        #pragma unroll
        for (int i = t; i < NNv * OQ / 4; i += 128) dst[i] = src[i];
        const float* gsrc = g_G + ((size_t)b * NNv + p) * CCv;
        #pragma unroll
        for (int i = t; i < CCv; i += 128) {
            float g = gsrc[i];
            Gd[i] = pk(g, g);
        }
    }
    __syncthreads();

    float inv = g_invl2[b];
    int q0 = t, q1 = t + 128, q2 = t + 256, q3 = t + 384;
    ull flA[OQ], flB[OQ];
    #pragma unroll
    for (int o = 0; o < OQ; o++) {
        flA[o] = pk(Fls[q0 * OQ + o], Fls[q1 * OQ + o]);
        flB[o] = pk(Fls[q2 * OQ + o], Fls[q3 * OQ + o]);
    }
    float m0 = -1e30f, m1 = -1e30f, m2 = -1e30f, m3 = -1e30f;
    #pragma unroll 2
    for (int c = 0; c < C4v; c++) {
        ull g = Gd[c];
        ull a = mul2(flA[0], g);
        ull e = mul2(flB[0], g);
        #pragma unroll
        for (int o = 1; o < OQ; o++) {
            g = Gd[o * C4v + c];       // same addr across threads -> broadcast
            a = fma2(flA[o], g, a);
            e = fma2(flB[o], g, e);
        }
        float a0, a1, e0, e1;
        upk(a, a0, a1); upk(e, e0, e1);
        m0 = fmaxf(m0, a0); m1 = fmaxf(m1, a1);
        m2 = fmaxf(m2, e0); m3 = fmaxf(m3, e1);
    }
    float* Trow = g_T + ((size_t)b * NNv + p) * NNv;
    Trow[q0] = fmaxf(tanhf(m0 * inv), 0.f);
    Trow[q1] = fmaxf(tanhf(m1 * inv), 0.f);
    Trow[q2] = fmaxf(tanhf(m2 * inv), 0.f);
    Trow[q3] = fmaxf(tanhf(m3 * inv), 0.f);
}

// k3: per-b SGEMM  H[k][cc] = sum_n T[k][n] * G[n][cc]
// 128x128 tile, Kt=16, 256 threads, 8x8 microtile, cc-dim f32x2 packed.
// Bs padded to 136 floats/row: 544B row stride keeps LDS.128 16B-aligned,
// and 136 mod 32 = 8 makes the 4-way transpose stores bank-conflict-free.
__global__ void __launch_bounds__(256) k3() {
    int b = blockIdx.z;
    int cc0 = blockIdx.y * 128;
    int k0 = blockIdx.x * 128;
    const float* A  = g_G + (size_t)b * NNv * CCv;  // [n][cc]
    const float* Bm = g_T + (size_t)b * NNv * NNv;  // [k][n]
    float* Cm = g_H + (size_t)b * NNv * CCv;        // [k][cc]

    __shared__ float As[16][128];
    __shared__ float Bs[16][136];
    int t = threadIdx.x;
    int tx = t & 15, ty = t >> 4;   // tx -> cc (8 each), ty -> k (8 each)
    ull acc[4][8];
    #pragma unroll
    for (int i = 0; i < 4; i++)
        #pragma unroll
        for (int j = 0; j < 8; j++) acc[i][j] = 0ull;

    for (int n0 = 0; n0 < NNv; n0 += 16) {
        // stage A tile [16 n][128 cc]
        #pragma unroll
        for (int i = 0; i < 2; i++) {
            int idx = t + i * 256;
            int row = idx >> 5, col = (idx & 31) * 4;
            *(float4*)(&As[row][col]) =
                *(const float4*)(A + (size_t)(n0 + row) * CCv + cc0 + col);
        }
        // stage B tile transposed: Bs[n][k]
        #pragma unroll
        for (int i = 0; i < 2; i++) {
            int idx = t + i * 256;
            int k = idx >> 2, nn = (idx & 3) * 4;
            float4 v = *(const float4*)(Bm + (size_t)(k0 + k) * NNv + n0 + nn);
            Bs[nn + 0][k] = v.x; Bs[nn + 1][k] = v.y;
            Bs[nn + 2][k] = v.z; Bs[nn + 3][k] = v.w;
        }
        __syncthreads();
        #pragma unroll
        for (int kk = 0; kk < 16; kk++) {
            float4 aA = *(const float4*)(&As[kk][tx * 8]);
            float4 aB = *(const float4*)(&As[kk][tx * 8 + 4]);
            ull a0 = pk(aA.x, aA.y), a1 = pk(aA.z, aA.w);
            ull a2 = pk(aB.x, aB.y), a3 = pk(aB.z, aB.w);
            float4 bA = *(const float4*)(&Bs[kk][ty * 8]);
            float4 bB = *(const float4*)(&Bs[kk][ty * 8 + 4]);
            float bf[8] = {bA.x, bA.y, bA.z, bA.w, bB.x, bB.y, bB.z, bB.w};
            #pragma unroll
            for (int j = 0; j < 8; j++) {
                ull bp = pk(bf[j], bf[j]);
                acc[0][j] = fma2(a0, bp, acc[0][j]);
                acc[1][j] = fma2(a1, bp, acc[1][j]);
                acc[2][j] = fma2(a2, bp, acc[2][j]);
                acc[3][j] = fma2(a3, bp, acc[3][j]);
            }
        }
        __syncthreads();
    }
    #pragma unroll
    for (int j = 0; j < 8; j++) {
        float4 v0, v1;
        upk(acc[0][j], v0.x, v0.y); upk(acc[1][j], v0.z, v0.w);
        upk(acc[2][j], v1.x, v1.y); upk(acc[3][j], v1.z, v1.w);
        float* dst = Cm + (size_t)(k0 + ty * 8 + j) * CCv + cc0 + tx * 8;
        *(float4*)(dst) = v0;
        *(float4*)(dst + 4) = v1;
    }
}

// k4: xg[c][k] = inv * sum_o Fl[b][k][o] * H[b][k][o*64+c];
//     out[b][o][k] = b_gcn[o] + sum_c W_gcn[o][c] * xg[c][k]
__global__ void k4(const float* __restrict__ Wg, const float* __restrict__ bg,
                   float* __restrict__ out) {
    int k = blockIdx.x, b = blockIdx.y;
    __shared__ float Hs[CCv];
    __shared__ float xg[C4v];
    __shared__ float Wgs[C4v * C4v];
    __shared__ float Flk[OQ];
    int t = threadIdx.x;  // 128

    for (int i = t; i < CCv / 4; i += 128)
        ((float4*)Hs)[i] = ((const float4*)(g_H + ((size_t)b * NNv + k) * CCv))[i];
    for (int i = t; i < C4v * C4v / 4; i += 128)
        ((float4*)Wgs)[i] = ((const float4*)Wg)[i];
    if (t < OQ) Flk[t] = g_Fl[((size_t)b * NNv + k) * OQ + t];
    __syncthreads();

    float inv = g_invl2[b];
    if (t < C4v) {
        float s = 0.f;
        #pragma unroll
        for (int o = 0; o < OQ; o++) s += Flk[o] * Hs[o * C4v + t];
        xg[t] = s * inv;
    }
    __syncthreads();
    if (t < C4v) {
        float s = bg[t];
        #pragma unroll 16
        for (int c = 0; c < C4v; c++) s += Wgs[t * C4v + c] * xg[c];
        out[((size_t)b * C4v + t) * NNv + k] = s;
    }
}

extern "C" void kernel_launch(void* const* d_in, const int* in_sizes, int n_in,
                              void* d_out, int out_size) {
    const float* x  = (const float*)d_in[0];
    const float* Wc = (const float*)d_in[1];
    const float* bc = (const float*)d_in[2];
    const float* Wg = (const float*)d_in[3];
    const float* bg = (const float*)d_in[4];
    float* out = (float*)d_out;

    k_zero<<<1, 256>>>();
    k1<<<dim3(NNv, BB), 128>>>(x, Wc, bc);
    k1b<<<BB, 32>>>();
    k2<<<dim3(NNv, BB), 128>>>();
    k3<<<dim3(NNv / 128, CCv / 128, BB), 256>>>();
    k4<<<dim3(NNv, BB), 128>>>(Wg, bg, out);
}

// round 5
// speedup vs baseline: 1.0855x; 1.0102x over previous
#include <cuda_runtime.h>
#include <math.h>

#define BB 8
#define C4v 64
#define OQ 16
#define NNv 512
#define LL 12
#define CCv (OQ * C4v)   // 1024

typedef unsigned long long ull;

__device__ __forceinline__ ull pk(float lo, float hi) {
    ull r; asm("mov.b64 %0,{%1,%2};" : "=l"(r) : "f"(lo), "f"(hi)); return r;
}
__device__ __forceinline__ void upk(ull v, float& lo, float& hi) {
    asm("mov.b64 {%0,%1},%2;" : "=f"(lo), "=f"(hi) : "l"(v));
}
__device__ __forceinline__ ull fma2(ull a, ull b, ull c) {
    ull d; asm("fma.rn.f32x2 %0,%1,%2,%3;" : "=l"(d) : "l"(a), "l"(b), "l"(c)); return d;
}
__device__ __forceinline__ ull mul2(ull a, ull b) {
    ull d; asm("mul.rn.f32x2 %0,%1,%2;" : "=l"(d) : "l"(a), "l"(b)); return d;
}

// Scratch (device globals: allocation-free per harness rules)
__device__ float g_G[BB * NNv * CCv];   // [b][n][c'][c]  16.8 MB
__device__ float g_Fl[BB * NNv * OQ];   // [b][n][c']
__device__ float g_T[BB * NNv * NNv];   // [b][k][n]      8.4 MB
__device__ float g_H[BB * NNv * CCv];   // [b][k][cc]     16.8 MB
__device__ float g_xx[BB * OQ];
__device__ float g_yy[BB * OQ];
__device__ float g_invl2[BB];

__global__ void k_zero() {
    int t = threadIdx.x;
    if (t < BB * OQ) { g_xx[t] = 0.f; g_yy[t] = 0.f; }
}

// k1: Fc (local), Fl, G, norm partials. Block per (n, b), 128 threads.
__global__ void k1(const float* __restrict__ x, const float* __restrict__ Wc,
                   const float* __restrict__ bc) {
    int n = blockIdx.x, b = blockIdx.y;
    __shared__ float xs[C4v * LL];   // [c][l]
    __shared__ float Ws[OQ * C4v];   // [o][c]
    __shared__ float Fc[OQ * LL];    // [o][l]
    int t = threadIdx.x;

    for (int i = t; i < C4v * LL; i += 128) {
        int c = i / LL, l = i % LL;
        xs[i] = x[((b * C4v + c) * NNv + n) * LL + l];
    }
    for (int i = t; i < OQ * C4v; i += 128) Ws[i] = Wc[i];
    __syncthreads();

    for (int i = t; i < OQ * LL; i += 128) {
        int o = i / LL, l = i % LL;
        float s = bc[o];
        #pragma unroll 16
        for (int c = 0; c < C4v; c++) s += Ws[o * C4v + c] * xs[c * LL + l];
        Fc[i] = s;
    }
    __syncthreads();

    // G[b][n][o][c] = sum_l Fc[o][l] * x[c][l]
    for (int i = t; i < CCv; i += 128) {
        int o = i >> 6, c = i & 63;
        float s = 0.f;
        #pragma unroll
        for (int l = 0; l < LL; l++) s += Fc[o * LL + l] * xs[c * LL + l];
        g_G[(b * NNv + n) * CCv + i] = s;
    }
    if (t < OQ) {
        float fl = Fc[t * LL + (LL - 1)];
        g_Fl[(b * NNv + n) * OQ + t] = fl;
        float ys = 0.f;
        #pragma unroll
        for (int l = 0; l < LL; l++) { float v = Fc[t * LL + l]; ys += v * v; }
        atomicAdd(&g_xx[b * OQ + t], fl * fl);
        atomicAdd(&g_yy[b * OQ + t], ys);
    }
}

// k1b: inv_l2[b] = 1 / sum_c sqrt(xx)*sqrt(yy)
__global__ void k1b() {
    int b = blockIdx.x;
    int t = threadIdx.x;  // 32
    float v = 0.f;
    if (t < OQ) v = sqrtf(g_xx[b * OQ + t]) * sqrtf(g_yy[b * OQ + t]);
    #pragma unroll
    for (int s = 16; s > 0; s >>= 1) v += __shfl_down_sync(0xffffffffu, v, s);
    if (t == 0) g_invl2[b] = 1.0f / v;
}

// k2: T[b][p][q] = relu(tanh(inv * max_c sum_o Fl[b][q][o] * G[b][p][o][c]))
// Block per (p, b), 128 threads, 4 q per thread (f32x2 packed over q-pairs),
// 2 c per iteration via one broadcast LDS.128 on duplicated (g,g) pairs.
__global__ void __launch_bounds__(128) k2() {
    int p = blockIdx.x, b = blockIdx.y;
    __shared__ float Fls[NNv * OQ];            // 32 KB  [q][o]
    __shared__ __align__(16) ull Gd[OQ * C4v]; // 8 KB  (g,g) duplicated pairs
    int t = threadIdx.x;  // 128

    {
        const float4* src = (const float4*)(g_Fl + (size_t)b * NNv * OQ);
        float4* dst = (float4*)Fls;
        #pragma unroll
        for (int i = t; i < NNv * OQ / 4; i += 128) dst[i] = src[i];
        const float* gsrc = g_G + ((size_t)b * NNv + p) * CCv;
        #pragma unroll
        for (int i = t; i < CCv; i += 128) {
            float g = gsrc[i];
            Gd[i] = pk(g, g);
        }
    }
    __syncthreads();

    float inv = g_invl2[b];
    int q0 = t, q1 = t + 128, q2 = t + 256, q3 = t + 384;
    ull flA[OQ], flB[OQ];
    #pragma unroll
    for (int o = 0; o < OQ; o++) {
        flA[o] = pk(Fls[q0 * OQ + o], Fls[q1 * OQ + o]);
        flB[o] = pk(Fls[q2 * OQ + o], Fls[q3 * OQ + o]);
    }
    float m0 = -1e30f, m1 = -1e30f, m2 = -1e30f, m3 = -1e30f;
    for (int c = 0; c < C4v; c += 2) {
        ulonglong2 g = *(const ulonglong2*)(&Gd[c]);
        ull aX = mul2(flA[0], g.x);
        ull aY = mul2(flA[0], g.y);
        ull eX = mul2(flB[0], g.x);
        ull eY = mul2(flB[0], g.y);
        #pragma unroll
        for (int o = 1; o < OQ; o++) {
            g = *(const ulonglong2*)(&Gd[o * C4v + c]);  // broadcast LDS.128
            aX = fma2(flA[o], g.x, aX);
            aY = fma2(flA[o], g.y, aY);
            eX = fma2(flB[o], g.x, eX);
            eY = fma2(flB[o], g.y, eY);
        }
        float v0, v1;
        upk(aX, v0, v1); m0 = fmaxf(m0, v0); m1 = fmaxf(m1, v1);
        upk(aY, v0, v1); m0 = fmaxf(m0, v0); m1 = fmaxf(m1, v1);
        upk(eX, v0, v1); m2 = fmaxf(m2, v0); m3 = fmaxf(m3, v1);
        upk(eY, v0, v1); m2 = fmaxf(m2, v0); m3 = fmaxf(m3, v1);
    }
    float* Trow = g_T + ((size_t)b * NNv + p) * NNv;
    Trow[q0] = fmaxf(tanhf(m0 * inv), 0.f);
    Trow[q1] = fmaxf(tanhf(m1 * inv), 0.f);
    Trow[q2] = fmaxf(tanhf(m2 * inv), 0.f);
    Trow[q3] = fmaxf(tanhf(m3 * inv), 0.f);
}

// k3: per-b SGEMM  H[k][cc] = sum_n T[k][n] * G[n][cc]
// 128x128 tile, Kt=16, 256 threads, 8x8 microtile (cc split 4+4 for
// conflict-free LDS.128), B staged untransposed Bs[k][nn] (broadcast scalar
// reads), register prefetch of next tile.
__global__ void __launch_bounds__(256) k3() {
    int b = blockIdx.z;
    int cc0 = blockIdx.y * 128;
    int k0 = blockIdx.x * 128;
    const float* A  = g_G + (size_t)b * NNv * CCv;  // [n][cc]
    const float* Bm = g_T + (size_t)b * NNv * NNv;  // [k][n]
    float* Cm = g_H + (size_t)b * NNv * CCv;        // [k][cc]

    __shared__ float As[16][128];
    __shared__ float Bs[128][21];
    int t = threadIdx.x;
    int tx = t & 15, ty = t >> 4;   // tx -> cc (4+4), ty -> k (8)

    float4 pA[2], pB[2];
    #pragma unroll
    for (int i = 0; i < 2; i++) {
        int idx = t + i * 256;
        int row = idx >> 5, col = (idx & 31) * 4;
        pA[i] = *(const float4*)(A + (size_t)row * CCv + cc0 + col);
        int k = idx >> 2, nn = (idx & 3) * 4;
        pB[i] = *(const float4*)(Bm + (size_t)(k0 + k) * NNv + nn);
    }

    ull acc[4][8];
    #pragma unroll
    for (int i = 0; i < 4; i++)
        #pragma unroll
        for (int j = 0; j < 8; j++) acc[i][j] = 0ull;

    for (int n0 = 0; n0 < NNv; n0 += 16) {
        // commit staged registers to smem
        #pragma unroll
        for (int i = 0; i < 2; i++) {
            int idx = t + i * 256;
            int row = idx >> 5, col = (idx & 31) * 4;
            *(float4*)(&As[row][col]) = pA[i];
            int k = idx >> 2, nn = (idx & 3) * 4;
            Bs[k][nn + 0] = pB[i].x; Bs[k][nn + 1] = pB[i].y;
            Bs[k][nn + 2] = pB[i].z; Bs[k][nn + 3] = pB[i].w;
        }
        __syncthreads();
        // prefetch next tile while computing on this one
        if (n0 + 16 < NNv) {
            #pragma unroll
            for (int i = 0; i < 2; i++) {
                int idx = t + i * 256;
                int row = idx >> 5, col = (idx & 31) * 4;
                pA[i] = *(const float4*)(A + (size_t)(n0 + 16 + row) * CCv + cc0 + col);
                int k = idx >> 2, nn = (idx & 3) * 4;
                pB[i] = *(const float4*)(Bm + (size_t)(k0 + k) * NNv + n0 + 16 + nn);
            }
        }
        #pragma unroll
        for (int kk = 0; kk < 16; kk++) {
            float4 aA = *(const float4*)(&As[kk][tx * 4]);        // conflict-free
            float4 aB = *(const float4*)(&As[kk][64 + tx * 4]);   // conflict-free
            ull a0 = pk(aA.x, aA.y), a1 = pk(aA.z, aA.w);
            ull a2 = pk(aB.x, aB.y), a3 = pk(aB.z, aB.w);
            #pragma unroll
            for (int j = 0; j < 8; j++) {
                float bv = Bs[ty * 8 + j][kk];                    // broadcast
                ull bp = pk(bv, bv);
                acc[0][j] = fma2(a0, bp, acc[0][j]);
                acc[1][j] = fma2(a1, bp, acc[1][j]);
                acc[2][j] = fma2(a2, bp, acc[2][j]);
                acc[3][j] = fma2(a3, bp, acc[3][j]);
            }
        }
        __syncthreads();
    }
    #pragma unroll
    for (int j = 0; j < 8; j++) {
        float4 v0, v1;
        upk(acc[0][j], v0.x, v0.y); upk(acc[1][j], v0.z, v0.w);
        upk(acc[2][j], v1.x, v1.y); upk(acc[3][j], v1.z, v1.w);
        float* dst = Cm + (size_t)(k0 + ty * 8 + j) * CCv + cc0;
        *(float4*)(dst + tx * 4) = v0;
        *(float4*)(dst + 64 + tx * 4) = v1;
    }
}

// k4: xg[c][k] = inv * sum_o Fl[b][k][o] * H[b][k][o*64+c];
//     out[b][o][k] = b_gcn[o] + sum_c W_gcn[o][c] * xg[c][k]
__global__ void k4(const float* __restrict__ Wg, const float* __restrict__ bg,
                   float* __restrict__ out) {
    int k = blockIdx.x, b = blockIdx.y;
    __shared__ float Hs[CCv];
    __shared__ float xg[C4v];
    __shared__ float Wgs[C4v * C4v];
    __shared__ float Flk[OQ];
    int t = threadIdx.x;  // 128

    for (int i = t; i < CCv / 4; i += 128)
        ((float4*)Hs)[i] = ((const float4*)(g_H + ((size_t)b * NNv + k) * CCv))[i];
    for (int i = t; i < C4v * C4v / 4; i += 128)
        ((float4*)Wgs)[i] = ((const float4*)Wg)[i];
    if (t < OQ) Flk[t] = g_Fl[((size_t)b * NNv + k) * OQ + t];
    __syncthreads();

    float inv = g_invl2[b];
    if (t < C4v) {
        float s = 0.f;
        #pragma unroll
        for (int o = 0; o < OQ; o++) s += Flk[o] * Hs[o * C4v + t];
        xg[t] = s * inv;
    }
    __syncthreads();
    if (t < C4v) {
        float s = bg[t];
        #pragma unroll 16
        for (int c = 0; c < C4v; c++) s += Wgs[t * C4v + c] * xg[c];
        out[((size_t)b * C4v + t) * NNv + k] = s;
    }
}

extern "C" void kernel_launch(void* const* d_in, const int* in_sizes, int n_in,
                              void* d_out, int out_size) {
    const float* x  = (const float*)d_in[0];
    const float* Wc = (const float*)d_in[1];
    const float* bc = (const float*)d_in[2];
    const float* Wg = (const float*)d_in[3];
    const float* bg = (const float*)d_in[4];
    float* out = (float*)d_out;

    k_zero<<<1, 256>>>();
    k1<<<dim3(NNv, BB), 128>>>(x, Wc, bc);
    k1b<<<BB, 32>>>();
    k2<<<dim3(NNv, BB), 128>>>();
    k3<<<dim3(NNv / 128, CCv / 128, BB), 256>>>();
    k4<<<dim3(NNv, BB), 128>>>(Wg, bg, out);
}

// round 6
// speedup vs baseline: 1.1126x; 1.0249x over previous
#include <cuda_runtime.h>
#include <math.h>

#define BB 8
#define C4v 64
#define OQ 16
#define NNv 512
#define LL 12
#define CCv (OQ * C4v)   // 1024

typedef unsigned long long ull;

__device__ __forceinline__ ull pk(float lo, float hi) {
    ull r; asm("mov.b64 %0,{%1,%2};" : "=l"(r) : "f"(lo), "f"(hi)); return r;
}
__device__ __forceinline__ void upk(ull v, float& lo, float& hi) {
    asm("mov.b64 {%0,%1},%2;" : "=f"(lo), "=f"(hi) : "l"(v));
}
__device__ __forceinline__ ull fma2(ull a, ull b, ull c) {
    ull d; asm("fma.rn.f32x2 %0,%1,%2,%3;" : "=l"(d) : "l"(a), "l"(b), "l"(c)); return d;
}
__device__ __forceinline__ ull mul2(ull a, ull b) {
    ull d; asm("mul.rn.f32x2 %0,%1,%2;" : "=l"(d) : "l"(a), "l"(b)); return d;
}

// Scratch (device globals: allocation-free per harness rules)
__device__ float g_G[BB * NNv * CCv];   // [b][n][c'][c]  16.8 MB
__device__ float g_Fl[BB * NNv * OQ];   // [b][n][c']
__device__ float g_T[BB * NNv * NNv];   // [b][k][n]      8.4 MB
__device__ float g_H[BB * NNv * CCv];   // [b][k][cc]     16.8 MB
__device__ float g_xx[BB * OQ];
__device__ float g_yy[BB * OQ];
__device__ float g_invl2[BB];

__global__ void k_zero() {
    int t = threadIdx.x;
    if (t < BB * OQ) { g_xx[t] = 0.f; g_yy[t] = 0.f; }
}

// k1: Fc (local), Fl, G, norm partials. Block per (n, b), 128 threads.
__global__ void k1(const float* __restrict__ x, const float* __restrict__ Wc,
                   const float* __restrict__ bc) {
    int n = blockIdx.x, b = blockIdx.y;
    __shared__ float xs[C4v * LL];   // [c][l]
    __shared__ float Ws[OQ * C4v];   // [o][c]
    __shared__ float Fc[OQ * LL];    // [o][l]
    int t = threadIdx.x;

    for (int i = t; i < C4v * LL; i += 128) {
        int c = i / LL, l = i % LL;
        xs[i] = x[((b * C4v + c) * NNv + n) * LL + l];
    }
    for (int i = t; i < OQ * C4v; i += 128) Ws[i] = Wc[i];
    __syncthreads();

    for (int i = t; i < OQ * LL; i += 128) {
        int o = i / LL, l = i % LL;
        float s = bc[o];
        #pragma unroll 16
        for (int c = 0; c < C4v; c++) s += Ws[o * C4v + c] * xs[c * LL + l];
        Fc[i] = s;
    }
    __syncthreads();

    // G[b][n][o][c] = sum_l Fc[o][l] * x[c][l]
    for (int i = t; i < CCv; i += 128) {
        int o = i >> 6, c = i & 63;
        float s = 0.f;
        #pragma unroll
        for (int l = 0; l < LL; l++) s += Fc[o * LL + l] * xs[c * LL + l];
        g_G[(b * NNv + n) * CCv + i] = s;
    }
    if (t < OQ) {
        float fl = Fc[t * LL + (LL - 1)];
        g_Fl[(b * NNv + n) * OQ + t] = fl;
        float ys = 0.f;
        #pragma unroll
        for (int l = 0; l < LL; l++) { float v = Fc[t * LL + l]; ys += v * v; }
        atomicAdd(&g_xx[b * OQ + t], fl * fl);
        atomicAdd(&g_yy[b * OQ + t], ys);
    }
}

// k1b: inv_l2[b] = 1 / sum_c sqrt(xx)*sqrt(yy)
__global__ void k1b() {
    int b = blockIdx.x;
    int t = threadIdx.x;  // 32
    float v = 0.f;
    if (t < OQ) v = sqrtf(g_xx[b * OQ + t]) * sqrtf(g_yy[b * OQ + t]);
    #pragma unroll
    for (int s = 16; s > 0; s >>= 1) v += __shfl_down_sync(0xffffffffu, v, s);
    if (t == 0) g_invl2[b] = 1.0f / v;
}

// k2: T[b][p][q] = relu(tanh(inv * max_c sum_o Fl[b][q][o] * G[b][p][o][c]))
// Block per (p, b), 128 threads. Thread t owns q = 4t..4t+3 (f32x2 packed
// pairs), Fl rows loaded gmem->regs directly (256B contiguous per thread,
// L2-resident). Only G stays in smem (8KB) -> high occupancy.
__global__ void __launch_bounds__(128) k2() {
    int p = blockIdx.x, b = blockIdx.y;
    __shared__ __align__(16) ull Gd[OQ * C4v]; // 8 KB  (g,g) duplicated pairs
    int t = threadIdx.x;  // 128

    {
        const float* gsrc = g_G + ((size_t)b * NNv + p) * CCv;
        #pragma unroll
        for (int i = t; i < CCv; i += 128) {
            float g = gsrc[i];
            Gd[i] = pk(g, g);
        }
    }

    // Load 4 Fl rows (q = 4t+0..3) straight into packed registers.
    const float4* flp = (const float4*)(g_Fl + ((size_t)b * NNv + 4 * t) * OQ);
    ull flA[OQ], flB[OQ];
    #pragma unroll
    for (int o4 = 0; o4 < 4; o4++) {
        float4 r0 = __ldg(flp + o4);          // row 4t
        float4 r1 = __ldg(flp + 4 + o4);      // row 4t+1
        float4 r2 = __ldg(flp + 8 + o4);      // row 4t+2
        float4 r3 = __ldg(flp + 12 + o4);     // row 4t+3
        flA[4 * o4 + 0] = pk(r0.x, r1.x); flB[4 * o4 + 0] = pk(r2.x, r3.x);
        flA[4 * o4 + 1] = pk(r0.y, r1.y); flB[4 * o4 + 1] = pk(r2.y, r3.y);
        flA[4 * o4 + 2] = pk(r0.z, r1.z); flB[4 * o4 + 2] = pk(r2.z, r3.z);
        flA[4 * o4 + 3] = pk(r0.w, r1.w); flB[4 * o4 + 3] = pk(r2.w, r3.w);
    }
    __syncthreads();

    float inv = g_invl2[b];
    float m0 = -1e30f, m1 = -1e30f, m2 = -1e30f, m3 = -1e30f;
    for (int c = 0; c < C4v; c += 2) {
        ulonglong2 g = *(const ulonglong2*)(&Gd[c]);
        ull aX = mul2(flA[0], g.x);
        ull aY = mul2(flA[0], g.y);
        ull eX = mul2(flB[0], g.x);
        ull eY = mul2(flB[0], g.y);
        #pragma unroll
        for (int o = 1; o < OQ; o++) {
            g = *(const ulonglong2*)(&Gd[o * C4v + c]);  // broadcast LDS.128
            aX = fma2(flA[o], g.x, aX);
            aY = fma2(flA[o], g.y, aY);
            eX = fma2(flB[o], g.x, eX);
            eY = fma2(flB[o], g.y, eY);
        }
        float v0, v1;
        upk(aX, v0, v1); m0 = fmaxf(m0, v0); m1 = fmaxf(m1, v1);
        upk(aY, v0, v1); m0 = fmaxf(m0, v0); m1 = fmaxf(m1, v1);
        upk(eX, v0, v1); m2 = fmaxf(m2, v0); m3 = fmaxf(m3, v1);
        upk(eY, v0, v1); m2 = fmaxf(m2, v0); m3 = fmaxf(m3, v1);
    }
    float4 res;
    res.x = fmaxf(tanhf(m0 * inv), 0.f);
    res.y = fmaxf(tanhf(m1 * inv), 0.f);
    res.z = fmaxf(tanhf(m2 * inv), 0.f);
    res.w = fmaxf(tanhf(m3 * inv), 0.f);
    *(float4*)(g_T + ((size_t)b * NNv + p) * NNv + 4 * t) = res;
}

// k3: per-b SGEMM  H[k][cc] = sum_n T[k][n] * G[n][cc]
// 128x128 tile, Kt=16, 256 threads, 8x8 microtile (cc split 4+4 for
// conflict-free LDS.128), B staged untransposed Bs[k][nn] (broadcast scalar
// reads), register prefetch of next tile. 2 blocks/SM pinned.
__global__ void __launch_bounds__(256, 2) k3() {
    int b = blockIdx.z;
    int cc0 = blockIdx.y * 128;
    int k0 = blockIdx.x * 128;
    const float* A  = g_G + (size_t)b * NNv * CCv;  // [n][cc]
    const float* Bm = g_T + (size_t)b * NNv * NNv;  // [k][n]
    float* Cm = g_H + (size_t)b * NNv * CCv;        // [k][cc]

    __shared__ float As[16][128];
    __shared__ float Bs[128][21];
    int t = threadIdx.x;
    int tx = t & 15, ty = t >> 4;   // tx -> cc (4+4), ty -> k (8)

    float4 pA[2], pB[2];
    #pragma unroll
    for (int i = 0; i < 2; i++) {
        int idx = t + i * 256;
        int row = idx >> 5, col = (idx & 31) * 4;
        pA[i] = *(const float4*)(A + (size_t)row * CCv + cc0 + col);
        int k = idx >> 2, nn = (idx & 3) * 4;
        pB[i] = *(const float4*)(Bm + (size_t)(k0 + k) * NNv + nn);
    }

    ull acc[4][8];
    #pragma unroll
    for (int i = 0; i < 4; i++)
        #pragma unroll
        for (int j = 0; j < 8; j++) acc[i][j] = 0ull;

    for (int n0 = 0; n0 < NNv; n0 += 16) {
        // commit staged registers to smem
        #pragma unroll
        for (int i = 0; i < 2; i++) {
            int idx = t + i * 256;
            int row = idx >> 5, col = (idx & 31) * 4;
            *(float4*)(&As[row][col]) = pA[i];
            int k = idx >> 2, nn = (idx & 3) * 4;
            Bs[k][nn + 0] = pB[i].x; Bs[k][nn + 1] = pB[i].y;
            Bs[k][nn + 2] = pB[i].z; Bs[k][nn + 3] = pB[i].w;
        }
        __syncthreads();
        // prefetch next tile while computing on this one
        if (n0 + 16 < NNv) {
            #pragma unroll
            for (int i = 0; i < 2; i++) {
                int idx = t + i * 256;
                int row = idx >> 5, col = (idx & 31) * 4;
                pA[i] = *(const float4*)(A + (size_t)(n0 + 16 + row) * CCv + cc0 + col);
                int k = idx >> 2, nn = (idx & 3) * 4;
                pB[i] = *(const float4*)(Bm + (size_t)(k0 + k) * NNv + n0 + 16 + nn);
            }
        }
        #pragma unroll
        for (int kk = 0; kk < 16; kk++) {
            float4 aA = *(const float4*)(&As[kk][tx * 4]);        // conflict-free
            float4 aB = *(const float4*)(&As[kk][64 + tx * 4]);   // conflict-free
            ull a0 = pk(aA.x, aA.y), a1 = pk(aA.z, aA.w);
            ull a2 = pk(aB.x, aB.y), a3 = pk(aB.z, aB.w);
            #pragma unroll
            for (int j = 0; j < 8; j++) {
                float bv = Bs[ty * 8 + j][kk];                    // broadcast
                ull bp = pk(bv, bv);
                acc[0][j] = fma2(a0, bp, acc[0][j]);
                acc[1][j] = fma2(a1, bp, acc[1][j]);
                acc[2][j] = fma2(a2, bp, acc[2][j]);
                acc[3][j] = fma2(a3, bp, acc[3][j]);
            }
        }
        __syncthreads();
    }
    #pragma unroll
    for (int j = 0; j < 8; j++) {
        float4 v0, v1;
        upk(acc[0][j], v0.x, v0.y); upk(acc[1][j], v0.z, v0.w);
        upk(acc[2][j], v1.x, v1.y); upk(acc[3][j], v1.z, v1.w);
        float* dst = Cm + (size_t)(k0 + ty * 8 + j) * CCv + cc0;
        *(float4*)(dst + tx * 4) = v0;
        *(float4*)(dst + 64 + tx * 4) = v1;
    }
}

// k4: xg[c][k] = inv * sum_o Fl[b][k][o] * H[b][k][o*64+c];
//     out[b][o][k] = b_gcn[o] + sum_c W_gcn[o][c] * xg[c][k]
__global__ void k4(const float* __restrict__ Wg, const float* __restrict__ bg,
                   float* __restrict__ out) {
    int k = blockIdx.x, b = blockIdx.y;
    __shared__ float Hs[CCv];
    __shared__ float xg[C4v];
    __shared__ float Wgs[C4v * C4v];
    __shared__ float Flk[OQ];
    int t = threadIdx.x;  // 128

    for (int i = t; i < CCv / 4; i += 128)
        ((float4*)Hs)[i] = ((const float4*)(g_H + ((size_t)b * NNv + k) * CCv))[i];
    for (int i = t; i < C4v * C4v / 4; i += 128)
        ((float4*)Wgs)[i] = ((const float4*)Wg)[i];
    if (t < OQ) Flk[t] = g_Fl[((size_t)b * NNv + k) * OQ + t];
    __syncthreads();

    float inv = g_invl2[b];
    if (t < C4v) {
        float s = 0.f;
        #pragma unroll
        for (int o = 0; o < OQ; o++) s += Flk[o] * Hs[o * C4v + t];
        xg[t] = s * inv;
    }
    __syncthreads();
    if (t < C4v) {
        float s = bg[t];
        #pragma unroll 16
        for (int c = 0; c < C4v; c++) s += Wgs[t * C4v + c] * xg[c];
        out[((size_t)b * C4v + t) * NNv + k] = s;
    }
}

extern "C" void kernel_launch(void* const* d_in, const int* in_sizes, int n_in,
                              void* d_out, int out_size) {
    const float* x  = (const float*)d_in[0];
    const float* Wc = (const float*)d_in[1];
    const float* bc = (const float*)d_in[2];
    const float* Wg = (const float*)d_in[3];
    const float* bg = (const float*)d_in[4];
    float* out = (float*)d_out;

    k_zero<<<1, 256>>>();
    k1<<<dim3(NNv, BB), 128>>>(x, Wc, bc);
    k1b<<<BB, 32>>>();
    k2<<<dim3(NNv, BB), 128>>>();
    k3<<<dim3(NNv / 128, CCv / 128, BB), 256>>>();
    k4<<<dim3(NNv, BB), 128>>>(Wg, bg, out);
}

// round 7
// speedup vs baseline: 1.2060x; 1.0839x over previous
#include <cuda_runtime.h>
#include <math.h>

#define BB 8
#define C4v 64
#define OQ 16
#define NNv 512
#define LL 12
#define CCv (OQ * C4v)   // 1024

typedef unsigned long long ull;

__device__ __forceinline__ ull pk(float lo, float hi) {
    ull r; asm("mov.b64 %0,{%1,%2};" : "=l"(r) : "f"(lo), "f"(hi)); return r;
}
__device__ __forceinline__ void upk(ull v, float& lo, float& hi) {
    asm("mov.b64 {%0,%1},%2;" : "=f"(lo), "=f"(hi) : "l"(v));
}
__device__ __forceinline__ ull fma2(ull a, ull b, ull c) {
    ull d; asm("fma.rn.f32x2 %0,%1,%2,%3;" : "=l"(d) : "l"(a), "l"(b), "l"(c)); return d;
}

// Scratch (device globals: allocation-free per harness rules)
__device__ float g_G[BB * NNv * CCv];   // [b][n][c'][c]  16.8 MB
__device__ float g_Fl[BB * NNv * OQ];   // [b][n][c']
__device__ float g_T[BB * NNv * NNv];   // [b][k][n]      8.4 MB
__device__ float g_H[BB * NNv * CCv];   // [b][k][cc]     16.8 MB
__device__ float g_xx[BB * OQ];
__device__ float g_yy[BB * OQ];
__device__ float g_invl2[BB];

__global__ void k_zero() {
    int t = threadIdx.x;
    if (t < BB * OQ) { g_xx[t] = 0.f; g_yy[t] = 0.f; }
}

// k1: Fc (local), Fl, G, norm partials. Block per (n, b), 128 threads.
__global__ void k1(const float* __restrict__ x, const float* __restrict__ Wc,
                   const float* __restrict__ bc) {
    int n = blockIdx.x, b = blockIdx.y;
    __shared__ float xs[C4v * LL];   // [c][l]
    __shared__ float Ws[OQ * C4v];   // [o][c]
    __shared__ float Fc[OQ * LL];    // [o][l]
    int t = threadIdx.x;

    for (int i = t; i < C4v * LL; i += 128) {
        int c = i / LL, l = i % LL;
        xs[i] = x[((b * C4v + c) * NNv + n) * LL + l];
    }
    for (int i = t; i < OQ * C4v; i += 128) Ws[i] = Wc[i];
    __syncthreads();

    for (int i = t; i < OQ * LL; i += 128) {
        int o = i / LL, l = i % LL;
        float s = bc[o];
        #pragma unroll 16
        for (int c = 0; c < C4v; c++) s += Ws[o * C4v + c] * xs[c * LL + l];
        Fc[i] = s;
    }
    __syncthreads();

    // G[b][n][o][c] = sum_l Fc[o][l] * x[c][l]
    for (int i = t; i < CCv; i += 128) {
        int o = i >> 6, c = i & 63;
        float s = 0.f;
        #pragma unroll
        for (int l = 0; l < LL; l++) s += Fc[o * LL + l] * xs[c * LL + l];
        g_G[(b * NNv + n) * CCv + i] = s;
    }
    if (t < OQ) {
        float fl = Fc[t * LL + (LL - 1)];
        g_Fl[(b * NNv + n) * OQ + t] = fl;
        float ys = 0.f;
        #pragma unroll
        for (int l = 0; l < LL; l++) { float v = Fc[t * LL + l]; ys += v * v; }
        atomicAdd(&g_xx[b * OQ + t], fl * fl);
        atomicAdd(&g_yy[b * OQ + t], ys);
    }
}

// k1b: inv_l2[b] = 1 / sum_c sqrt(xx)*sqrt(yy)
__global__ void k1b() {
    int b = blockIdx.x;
    int t = threadIdx.x;  // 32
    float v = 0.f;
    if (t < OQ) v = sqrtf(g_xx[b * OQ + t]) * sqrtf(g_yy[b * OQ + t]);
    #pragma unroll
    for (int s = 16; s > 0; s >>= 1) v += __shfl_down_sync(0xffffffffu, v, s);
    if (t == 0) g_invl2[b] = 1.0f / v;
}

// k2: T[b][p][q] = relu(tanh(inv * max_c sum_o Fl[b][q][o] * G[b][p][o][c]))
// Scheme C: 64 threads, block covers (p, 256-q half). Thread owns 4 q with Fl
// held as duplicated (f,f) register packs; G streamed as NATURAL (c,c+1)
// LDS.64 pairs (256B return) feeding 4 FMA2 chains -> 64B/FMA2 (crossbar
// parity with the FMA pipe), zero ALU dup cost.
__global__ void __launch_bounds__(64) k2() {
    int p = blockIdx.x, qh = blockIdx.y, b = blockIdx.z;
    __shared__ __align__(16) float Gs[OQ * C4v];  // natural [o][c], 4 KB
    int t = threadIdx.x;  // 64

    {
        const float4* gsrc = (const float4*)(g_G + ((size_t)b * NNv + p) * CCv);
        float4* gd = (float4*)Gs;
        #pragma unroll
        for (int i = t; i < CCv / 4; i += 64) gd[i] = gsrc[i];
    }

    // Fl dup packs for q = qh*256 + t + {0,64,128,192}
    ull fd[4][OQ];
    #pragma unroll
    for (int r = 0; r < 4; r++) {
        const float4* fp =
            (const float4*)(g_Fl + ((size_t)b * NNv + qh * 256 + t + r * 64) * OQ);
        #pragma unroll
        for (int i = 0; i < 4; i++) {
            float4 v = __ldg(fp + i);
            fd[r][4 * i + 0] = pk(v.x, v.x);
            fd[r][4 * i + 1] = pk(v.y, v.y);
            fd[r][4 * i + 2] = pk(v.z, v.z);
            fd[r][4 * i + 3] = pk(v.w, v.w);
        }
    }
    __syncthreads();

    float inv = g_invl2[b];
    float m0 = -1e30f, m1 = -1e30f, m2 = -1e30f, m3 = -1e30f;
    for (int cp = 0; cp < C4v / 2; cp++) {   // 32 natural c-pairs
        ull a0 = 0, a1 = 0, a2 = 0, a3 = 0;
        #pragma unroll
        for (int o = 0; o < OQ; o++) {
            ull g = *(const ull*)(Gs + o * C4v + 2 * cp);  // uniform LDS.64
            a0 = fma2(fd[0][o], g, a0);
            a1 = fma2(fd[1][o], g, a1);
            a2 = fma2(fd[2][o], g, a2);
            a3 = fma2(fd[3][o], g, a3);
        }
        float lo, hi;
        upk(a0, lo, hi); m0 = fmaxf(m0, fmaxf(lo, hi));
        upk(a1, lo, hi); m1 = fmaxf(m1, fmaxf(lo, hi));
        upk(a2, lo, hi); m2 = fmaxf(m2, fmaxf(lo, hi));
        upk(a3, lo, hi); m3 = fmaxf(m3, fmaxf(lo, hi));
    }
    float* Trow = g_T + ((size_t)b * NNv + p) * NNv + qh * 256 + t;
    Trow[0]   = fmaxf(tanhf(m0 * inv), 0.f);
    Trow[64]  = fmaxf(tanhf(m1 * inv), 0.f);
    Trow[128] = fmaxf(tanhf(m2 * inv), 0.f);
    Trow[192] = fmaxf(tanhf(m3 * inv), 0.f);
}

// k3: per-b SGEMM  H[k][cc] = sum_n T[k][n] * G[n][cc]
// 128x128 tile, Kt=16, 256 threads, 8x8 microtile (cc split 4+4), B staged
// untransposed Bs[k][nn] (broadcast scalar reads). Double-buffered smem:
// one __syncthreads per k-iter, next-tile loads overlap compute.
__global__ void __launch_bounds__(256, 2) k3() {
    int b = blockIdx.z;
    int cc0 = blockIdx.y * 128;
    int k0 = blockIdx.x * 128;
    const float* A  = g_G + (size_t)b * NNv * CCv;  // [n][cc]
    const float* Bm = g_T + (size_t)b * NNv * NNv;  // [k][n]
    float* Cm = g_H + (size_t)b * NNv * CCv;        // [k][cc]

    __shared__ float As[2][16][128];
    __shared__ float Bs[2][128][21];
    int t = threadIdx.x;
    int tx = t & 15, ty = t >> 4;   // tx -> cc (4+4), ty -> k (8)

    int r_arow = t >> 5, r_acol = (t & 31) * 4;          // A stage coords (×2)
    int r_arow2 = (t + 256) >> 5, r_acol2 = ((t + 256) & 31) * 4;
    int r_bk = t >> 2, r_bn = (t & 3) * 4;
    int r_bk2 = (t + 256) >> 2, r_bn2 = ((t + 256) & 3) * 4;

    // stage tile 0 into buffer 0
    {
        *(float4*)(&As[0][r_arow][r_acol]) =
            *(const float4*)(A + (size_t)r_arow * CCv + cc0 + r_acol);
        *(float4*)(&As[0][r_arow2][r_acol2]) =
            *(const float4*)(A + (size_t)r_arow2 * CCv + cc0 + r_acol2);
        float4 v = *(const float4*)(Bm + (size_t)(k0 + r_bk) * NNv + r_bn);
        Bs[0][r_bk][r_bn + 0] = v.x; Bs[0][r_bk][r_bn + 1] = v.y;
        Bs[0][r_bk][r_bn + 2] = v.z; Bs[0][r_bk][r_bn + 3] = v.w;
        v = *(const float4*)(Bm + (size_t)(k0 + r_bk2) * NNv + r_bn2);
        Bs[0][r_bk2][r_bn2 + 0] = v.x; Bs[0][r_bk2][r_bn2 + 1] = v.y;
        Bs[0][r_bk2][r_bn2 + 2] = v.z; Bs[0][r_bk2][r_bn2 + 3] = v.w;
    }
    __syncthreads();

    ull acc[4][8];
    #pragma unroll
    for (int i = 0; i < 4; i++)
        #pragma unroll
        for (int j = 0; j < 8; j++) acc[i][j] = 0ull;

    int buf = 0;
    for (int n0 = 0; n0 < NNv; n0 += 16) {
        // stage next tile into the other buffer (overlaps compute below)
        if (n0 + 16 < NNv) {
            int nb = buf ^ 1, nn0 = n0 + 16;
            *(float4*)(&As[nb][r_arow][r_acol]) =
                *(const float4*)(A + (size_t)(nn0 + r_arow) * CCv + cc0 + r_acol);
            *(float4*)(&As[nb][r_arow2][r_acol2]) =
                *(const float4*)(A + (size_t)(nn0 + r_arow2) * CCv + cc0 + r_acol2);
            float4 v = *(const float4*)(Bm + (size_t)(k0 + r_bk) * NNv + nn0 + r_bn);
            Bs[nb][r_bk][r_bn + 0] = v.x; Bs[nb][r_bk][r_bn + 1] = v.y;
            Bs[nb][r_bk][r_bn + 2] = v.z; Bs[nb][r_bk][r_bn + 3] = v.w;
            v = *(const float4*)(Bm + (size_t)(k0 + r_bk2) * NNv + nn0 + r_bn2);
            Bs[nb][r_bk2][r_bn2 + 0] = v.x; Bs[nb][r_bk2][r_bn2 + 1] = v.y;
            Bs[nb][r_bk2][r_bn2 + 2] = v.z; Bs[nb][r_bk2][r_bn2 + 3] = v.w;
        }
        #pragma unroll
        for (int kk = 0; kk < 16; kk++) {
            float4 aA = *(const float4*)(&As[buf][kk][tx * 4]);
            float4 aB = *(const float4*)(&As[buf][kk][64 + tx * 4]);
            ull a0 = pk(aA.x, aA.y), a1 = pk(aA.z, aA.w);
            ull a2 = pk(aB.x, aB.y), a3 = pk(aB.z, aB.w);
            #pragma unroll
            for (int j = 0; j < 8; j++) {
                float bv = Bs[buf][ty * 8 + j][kk];               // broadcast
                ull bp = pk(bv, bv);
                acc[0][j] = fma2(a0, bp, acc[0][j]);
                acc[1][j] = fma2(a1, bp, acc[1][j]);
                acc[2][j] = fma2(a2, bp, acc[2][j]);
                acc[3][j] = fma2(a3, bp, acc[3][j]);
            }
        }
        __syncthreads();
        buf ^= 1;
    }
    #pragma unroll
    for (int j = 0; j < 8; j++) {
        float4 v0, v1;
        upk(acc[0][j], v0.x, v0.y); upk(acc[1][j], v0.z, v0.w);
        upk(acc[2][j], v1.x, v1.y); upk(acc[3][j], v1.z, v1.w);
        float* dst = Cm + (size_t)(k0 + ty * 8 + j) * CCv + cc0;
        *(float4*)(dst + tx * 4) = v0;
        *(float4*)(dst + 64 + tx * 4) = v1;
    }
}

// k4: xg[c][k] = inv * sum_o Fl[b][k][o] * H[b][k][o*64+c];
//     out[b][o][k] = b_gcn[o] + sum_c W_gcn[o][c] * xg[c][k]
__global__ void k4(const float* __restrict__ Wg, const float* __restrict__ bg,
                   float* __restrict__ out) {
    int k = blockIdx.x, b = blockIdx.y;
    __shared__ float Hs[CCv];
    __shared__ float xg[C4v];
    __shared__ float Wgs[C4v * C4v];
    __shared__ float Flk[OQ];
    int t = threadIdx.x;  // 128

    for (int i = t; i < CCv / 4; i += 128)
        ((float4*)Hs)[i] = ((const float4*)(g_H + ((size_t)b * NNv + k) * CCv))[i];
    for (int i = t; i < C4v * C4v / 4; i += 128)
        ((float4*)Wgs)[i] = ((const float4*)Wg)[i];
    if (t < OQ) Flk[t] = g_Fl[((size_t)b * NNv + k) * OQ + t];
    __syncthreads();

    float inv = g_invl2[b];
    if (t < C4v) {
        float s = 0.f;
        #pragma unroll
        for (int o = 0; o < OQ; o++) s += Flk[o] * Hs[o * C4v + t];
        xg[t] = s * inv;
    }
    __syncthreads();
    if (t < C4v) {
        float s = bg[t];
        #pragma unroll 16
        for (int c = 0; c < C4v; c++) s += Wgs[t * C4v + c] * xg[c];
        out[((size_t)b * C4v + t) * NNv + k] = s;
    }
}

extern "C" void kernel_launch(void* const* d_in, const int* in_sizes, int n_in,
                              void* d_out, int out_size) {
    const float* x  = (const float*)d_in[0];
    const float* Wc = (const float*)d_in[1];
    const float* bc = (const float*)d_in[2];
    const float* Wg = (const float*)d_in[3];
    const float* bg = (const float*)d_in[4];
    float* out = (float*)d_out;

    k_zero<<<1, 256>>>();
    k1<<<dim3(NNv, BB), 128>>>(x, Wc, bc);
    k1b<<<BB, 32>>>();
    k2<<<dim3(NNv, 2, BB), 64>>>();
    k3<<<dim3(NNv / 128, CCv / 128, BB), 256>>>();
    k4<<<dim3(NNv, BB), 128>>>(Wg, bg, out);
}

// round 8
// speedup vs baseline: 1.2208x; 1.0123x over previous
#include <cuda_runtime.h>
#include <math.h>

#define BB 8
#define C4v 64
#define OQ 16
#define NNv 512
#define LL 12
#define CCv (OQ * C4v)   // 1024
#define KS 4             // k3 K-split factor

typedef unsigned long long ull;

__device__ __forceinline__ ull pk(float lo, float hi) {
    ull r; asm("mov.b64 %0,{%1,%2};" : "=l"(r) : "f"(lo), "f"(hi)); return r;
}
__device__ __forceinline__ void upk(ull v, float& lo, float& hi) {
    asm("mov.b64 {%0,%1},%2;" : "=f"(lo), "=f"(hi) : "l"(v));
}
__device__ __forceinline__ ull fma2(ull a, ull b, ull c) {
    ull d; asm("fma.rn.f32x2 %0,%1,%2,%3;" : "=l"(d) : "l"(a), "l"(b), "l"(c)); return d;
}

// Scratch (device globals: allocation-free per harness rules)
__device__ float g_G[BB * NNv * CCv];        // [b][n][c'][c]  16.8 MB
__device__ float g_Fl[BB * NNv * OQ];        // [b][n][c']
__device__ float g_T[BB * NNv * NNv];        // [b][k][n]      8.4 MB
__device__ float g_Hp[KS * BB * NNv * CCv];  // partial H, 67 MB
__device__ float g_xx[BB * OQ];
__device__ float g_yy[BB * OQ];
__device__ float g_invl2[BB];

__global__ void k_zero() {
    int t = threadIdx.x;
    if (t < BB * OQ) { g_xx[t] = 0.f; g_yy[t] = 0.f; }
}

// k1: Fc (local), Fl, G, norm partials. Block per (n, b), 128 threads.
__global__ void k1(const float* __restrict__ x, const float* __restrict__ Wc,
                   const float* __restrict__ bc) {
    int n = blockIdx.x, b = blockIdx.y;
    __shared__ float xs[C4v * LL];   // [c][l]
    __shared__ float Ws[OQ * C4v];   // [o][c]
    __shared__ float Fc[OQ * LL];    // [o][l]
    int t = threadIdx.x;

    for (int i = t; i < C4v * LL; i += 128) {
        int c = i / LL, l = i % LL;
        xs[i] = x[((b * C4v + c) * NNv + n) * LL + l];
    }
    for (int i = t; i < OQ * C4v; i += 128) Ws[i] = Wc[i];
    __syncthreads();

    for (int i = t; i < OQ * LL; i += 128) {
        int o = i / LL, l = i % LL;
        float s = bc[o];
        #pragma unroll 16
        for (int c = 0; c < C4v; c++) s += Ws[o * C4v + c] * xs[c * LL + l];
        Fc[i] = s;
    }
    __syncthreads();

    // G[b][n][o][c] = sum_l Fc[o][l] * x[c][l]
    for (int i = t; i < CCv; i += 128) {
        int o = i >> 6, c = i & 63;
        float s = 0.f;
        #pragma unroll
        for (int l = 0; l < LL; l++) s += Fc[o * LL + l] * xs[c * LL + l];
        g_G[(b * NNv + n) * CCv + i] = s;
    }
    if (t < OQ) {
        float fl = Fc[t * LL + (LL - 1)];
        g_Fl[(b * NNv + n) * OQ + t] = fl;
        float ys = 0.f;
        #pragma unroll
        for (int l = 0; l < LL; l++) { float v = Fc[t * LL + l]; ys += v * v; }
        atomicAdd(&g_xx[b * OQ + t], fl * fl);
        atomicAdd(&g_yy[b * OQ + t], ys);
    }
}

// k1b: inv_l2[b] = 1 / sum_c sqrt(xx)*sqrt(yy)
__global__ void k1b() {
    int b = blockIdx.x;
    int t = threadIdx.x;  // 32
    float v = 0.f;
    if (t < OQ) v = sqrtf(g_xx[b * OQ + t]) * sqrtf(g_yy[b * OQ + t]);
    #pragma unroll
    for (int s = 16; s > 0; s >>= 1) v += __shfl_down_sync(0xffffffffu, v, s);
    if (t == 0) g_invl2[b] = 1.0f / v;
}

// k2: T[b][p][q] = relu(tanh(inv * max_c sum_o Fl[b][q][o] * G[b][p][o][c]))
// 64 threads; block covers (p-pair, 256-q half). The 128-reg Fl dup-pack set
// is amortized over TWO p rows (two G tables in smem) -> 8 independent FMA2
// chains per thread, natural (c,c+1) LDS.64 feeds 8 FMA2 (32B/FMA2 return).
__global__ void __launch_bounds__(64) k2() {
    int pp = blockIdx.x * 2, qh = blockIdx.y, b = blockIdx.z;
    __shared__ __align__(16) float Gs0[OQ * C4v];  // 4 KB
    __shared__ __align__(16) float Gs1[OQ * C4v];  // 4 KB
    int t = threadIdx.x;  // 64

    {
        const float4* s0 = (const float4*)(g_G + ((size_t)b * NNv + pp) * CCv);
        const float4* s1 = (const float4*)(g_G + ((size_t)b * NNv + pp + 1) * CCv);
        #pragma unroll
        for (int i = t; i < CCv / 4; i += 64) {
            ((float4*)Gs0)[i] = s0[i];
            ((float4*)Gs1)[i] = s1[i];
        }
    }

    // Fl dup packs for q = qh*256 + t + {0,64,128,192}
    ull fd[4][OQ];
    #pragma unroll
    for (int r = 0; r < 4; r++) {
        const float4* fp =
            (const float4*)(g_Fl + ((size_t)b * NNv + qh * 256 + t + r * 64) * OQ);
        #pragma unroll
        for (int i = 0; i < 4; i++) {
            float4 v = __ldg(fp + i);
            fd[r][4 * i + 0] = pk(v.x, v.x);
            fd[r][4 * i + 1] = pk(v.y, v.y);
            fd[r][4 * i + 2] = pk(v.z, v.z);
            fd[r][4 * i + 3] = pk(v.w, v.w);
        }
    }
    __syncthreads();

    float inv = g_invl2[b];
    float m0[4], m1[4];
    #pragma unroll
    for (int r = 0; r < 4; r++) { m0[r] = -1e30f; m1[r] = -1e30f; }

    for (int cp = 0; cp < C4v / 2; cp++) {   // 32 natural c-pairs
        ull a0[4] = {0, 0, 0, 0};
        ull a1[4] = {0, 0, 0, 0};
        #pragma unroll
        for (int o = 0; o < OQ; o++) {
            ull ga = *(const ull*)(Gs0 + o * C4v + 2 * cp);  // uniform LDS.64
            ull gb = *(const ull*)(Gs1 + o * C4v + 2 * cp);
            #pragma unroll
            for (int r = 0; r < 4; r++) {
                a0[r] = fma2(fd[r][o], ga, a0[r]);
                a1[r] = fma2(fd[r][o], gb, a1[r]);
            }
        }
        #pragma unroll
        for (int r = 0; r < 4; r++) {
            float lo, hi;
            upk(a0[r], lo, hi); m0[r] = fmaxf(m0[r], fmaxf(lo, hi));
            upk(a1[r], lo, hi); m1[r] = fmaxf(m1[r], fmaxf(lo, hi));
        }
    }
    float* T0 = g_T + ((size_t)b * NNv + pp) * NNv + qh * 256 + t;
    float* T1 = T0 + NNv;
    #pragma unroll
    for (int r = 0; r < 4; r++) {
        T0[r * 64] = fmaxf(tanhf(m0[r] * inv), 0.f);
        T1[r * 64] = fmaxf(tanhf(m1[r] * inv), 0.f);
    }
}

// k3: per-b SGEMM  H[k][cc] = sum_n T[k][n] * G[n][cc], K-split 4 ways into
// partial buffers (1024 CTAs -> good wave balance). 128x128 tile, Kt=16,
// 256 threads, 8x8 microtile, double-buffered smem.
__global__ void __launch_bounds__(256, 2) k3() {
    int b = blockIdx.z >> 2;
    int ks = blockIdx.z & 3;
    int nbase = ks * (NNv / KS);            // 128 n per split
    int cc0 = blockIdx.y * 128;
    int k0 = blockIdx.x * 128;
    const float* A  = g_G + (size_t)b * NNv * CCv;  // [n][cc]
    const float* Bm = g_T + (size_t)b * NNv * NNv;  // [k][n]
    float* Cm = g_Hp + ((size_t)ks * BB + b) * NNv * CCv;  // [k][cc] partial

    __shared__ float As[2][16][128];
    __shared__ float Bs[2][128][21];
    int t = threadIdx.x;
    int tx = t & 15, ty = t >> 4;   // tx -> cc (4+4), ty -> k (8)

    int r_arow = t >> 5, r_acol = (t & 31) * 4;
    int r_arow2 = (t + 256) >> 5, r_acol2 = ((t + 256) & 31) * 4;
    int r_bk = t >> 2, r_bn = (t & 3) * 4;
    int r_bk2 = (t + 256) >> 2, r_bn2 = ((t + 256) & 3) * 4;

    // stage tile 0 into buffer 0
    {
        *(float4*)(&As[0][r_arow][r_acol]) =
            *(const float4*)(A + (size_t)(nbase + r_arow) * CCv + cc0 + r_acol);
        *(float4*)(&As[0][r_arow2][r_acol2]) =
            *(const float4*)(A + (size_t)(nbase + r_arow2) * CCv + cc0 + r_acol2);
        float4 v = *(const float4*)(Bm + (size_t)(k0 + r_bk) * NNv + nbase + r_bn);
        Bs[0][r_bk][r_bn + 0] = v.x; Bs[0][r_bk][r_bn + 1] = v.y;
        Bs[0][r_bk][r_bn + 2] = v.z; Bs[0][r_bk][r_bn + 3] = v.w;
        v = *(const float4*)(Bm + (size_t)(k0 + r_bk2) * NNv + nbase + r_bn2);
        Bs[0][r_bk2][r_bn2 + 0] = v.x; Bs[0][r_bk2][r_bn2 + 1] = v.y;
        Bs[0][r_bk2][r_bn2 + 2] = v.z; Bs[0][r_bk2][r_bn2 + 3] = v.w;
    }
    __syncthreads();

    ull acc[4][8];
    #pragma unroll
    for (int i = 0; i < 4; i++)
        #pragma unroll
        for (int j = 0; j < 8; j++) acc[i][j] = 0ull;

    int buf = 0;
    for (int n0 = 0; n0 < NNv / KS; n0 += 16) {
        if (n0 + 16 < NNv / KS) {
            int nb = buf ^ 1, nn0 = nbase + n0 + 16;
            *(float4*)(&As[nb][r_arow][r_acol]) =
                *(const float4*)(A + (size_t)(nn0 + r_arow) * CCv + cc0 + r_acol);
            *(float4*)(&As[nb][r_arow2][r_acol2]) =
                *(const float4*)(A + (size_t)(nn0 + r_arow2) * CCv + cc0 + r_acol2);
            float4 v = *(const float4*)(Bm + (size_t)(k0 + r_bk) * NNv + nn0 + r_bn);
            Bs[nb][r_bk][r_bn + 0] = v.x; Bs[nb][r_bk][r_bn + 1] = v.y;
            Bs[nb][r_bk][r_bn + 2] = v.z; Bs[nb][r_bk][r_bn + 3] = v.w;
            v = *(const float4*)(Bm + (size_t)(k0 + r_bk2) * NNv + nn0 + r_bn2);
            Bs[nb][r_bk2][r_bn2 + 0] = v.x; Bs[nb][r_bk2][r_bn2 + 1] = v.y;
            Bs[nb][r_bk2][r_bn2 + 2] = v.z; Bs[nb][r_bk2][r_bn2 + 3] = v.w;
        }
        #pragma unroll
        for (int kk = 0; kk < 16; kk++) {
            float4 aA = *(const float4*)(&As[buf][kk][tx * 4]);
            float4 aB = *(const float4*)(&As[buf][kk][64 + tx * 4]);
            ull a0 = pk(aA.x, aA.y), a1 = pk(aA.z, aA.w);
            ull a2 = pk(aB.x, aB.y), a3 = pk(aB.z, aB.w);
            #pragma unroll
            for (int j = 0; j < 8; j++) {
                float bv = Bs[buf][ty * 8 + j][kk];               // broadcast
                ull bp = pk(bv, bv);
                acc[0][j] = fma2(a0, bp, acc[0][j]);
                acc[1][j] = fma2(a1, bp, acc[1][j]);
                acc[2][j] = fma2(a2, bp, acc[2][j]);
                acc[3][j] = fma2(a3, bp, acc[3][j]);
            }
        }
        __syncthreads();
        buf ^= 1;
    }
    #pragma unroll
    for (int j = 0; j < 8; j++) {
        float4 v0, v1;
        upk(acc[0][j], v0.x, v0.y); upk(acc[1][j], v0.z, v0.w);
        upk(acc[2][j], v1.x, v1.y); upk(acc[3][j], v1.z, v1.w);
        float* dst = Cm + (size_t)(k0 + ty * 8 + j) * CCv + cc0;
        *(float4*)(dst + tx * 4) = v0;
        *(float4*)(dst + 64 + tx * 4) = v1;
    }
}

// k4: sum 4 H partials; xg[c] = inv * sum_o Fl[k][o] * H[k][o*64+c];
//     out[b][o][k] = b_gcn[o] + sum_c W_gcn[o][c] * xg[c]
__global__ void k4(const float* __restrict__ Wg, const float* __restrict__ bg,
                   float* __restrict__ out) {
    int k = blockIdx.x, b = blockIdx.y;
    __shared__ float Hs[CCv];
    __shared__ float xg[C4v];
    __shared__ float Wgs[C4v * C4v];
    __shared__ float Flk[OQ];
    int t = threadIdx.x;  // 128

    {
        size_t off = ((size_t)b * NNv + k) * CCv;
        size_t stride = (size_t)BB * NNv * CCv;
        const float4* h0 = (const float4*)(g_Hp + off);
        const float4* h1 = (const float4*)(g_Hp + off + stride);
        const float4* h2 = (const float4*)(g_Hp + off + 2 * stride);
        const float4* h3 = (const float4*)(g_Hp + off + 3 * stride);
        for (int i = t; i < CCv / 4; i += 128) {
            float4 a = h0[i], bv = h1[i], c = h2[i], d = h3[i];
            float4 s;
            s.x = (a.x + bv.x) + (c.x + d.x);
            s.y = (a.y + bv.y) + (c.y + d.y);
            s.z = (a.z + bv.z) + (c.z + d.z);
            s.w = (a.w + bv.w) + (c.w + d.w);
            ((float4*)Hs)[i] = s;
        }
    }
    for (int i = t; i < C4v * C4v / 4; i += 128)
        ((float4*)Wgs)[i] = ((const float4*)Wg)[i];
    if (t < OQ) Flk[t] = g_Fl[((size_t)b * NNv + k) * OQ + t];
    __syncthreads();

    float inv = g_invl2[b];
    if (t < C4v) {
        float s = 0.f;
        #pragma unroll
        for (int o = 0; o < OQ; o++) s += Flk[o] * Hs[o * C4v + t];
        xg[t] = s * inv;
    }
    __syncthreads();
    if (t < C4v) {
        float s = bg[t];
        #pragma unroll 16
        for (int c = 0; c < C4v; c++) s += Wgs[t * C4v + c] * xg[c];
        out[((size_t)b * C4v + t) * NNv + k] = s;
    }
}

extern "C" void kernel_launch(void* const* d_in, const int* in_sizes, int n_in,
                              void* d_out, int out_size) {
    const float* x  = (const float*)d_in[0];
    const float* Wc = (const float*)d_in[1];
    const float* bc = (const float*)d_in[2];
    const float* Wg = (const float*)d_in[3];
    const float* bg = (const float*)d_in[4];
    float* out = (float*)d_out;

    k_zero<<<1, 256>>>();
    k1<<<dim3(NNv, BB), 128>>>(x, Wc, bc);
    k1b<<<BB, 32>>>();
    k2<<<dim3(NNv / 2, 2, BB), 64>>>();
    k3<<<dim3(NNv / 128, CCv / 128, BB * KS), 256>>>();
    k4<<<dim3(NNv, BB), 128>>>(Wg, bg, out);
}